// round 6
// baseline (speedup 1.0000x reference)
#include <cuda_runtime.h>
#include <cuda_bf16.h>
#include <cstdint>

// ============================================================
// Problem constants
// ============================================================
#define N_NODES 100000
#define H_FEATS 128

// P[node][0:128] = h[node] @ W1[0:128,:]   (src half)
// P[node][128:256] = h[node] @ W1[128:256,:] (dst half)
__device__ float g_P[(size_t)N_NODES * 256];
__device__ int g_idx_is64;

// ============================================================
// Helpers
// ============================================================
__device__ __forceinline__ uint32_t cvt_rna_tf32(float x) {
    uint32_t r;
    asm("cvt.rna.tf32.f32 %0, %1;" : "=r"(r) : "f"(x));
    return r;
}

// mma.sync m16n8k8 tf32, f32 accumulate (sm_80 baseline PTX; legal on compute_103)
__device__ __forceinline__ void mma_tf32(float* c, const uint32_t* a, const uint32_t* b) {
    asm volatile(
        "mma.sync.aligned.m16n8k8.row.col.f32.tf32.tf32.f32 "
        "{%0,%1,%2,%3}, {%4,%5,%6,%7}, {%8,%9}, {%0,%1,%2,%3};"
        : "+f"(c[0]), "+f"(c[1]), "+f"(c[2]), "+f"(c[3])
        : "r"(a[0]), "r"(a[1]), "r"(a[2]), "r"(a[3]),
          "r"(b[0]), "r"(b[1]));
}

// ============================================================
// Kernel A: P[node][half*128 : half*128+128] = h[node] @ W1[half*128:+128, :]
// CTA tile: M=128 nodes, N=128 outs, K=128. 8 warps, warp tile 32x64.
// ============================================================
#define LDA 132  // 128 + 4 float padding

__global__ void __launch_bounds__(256, 1)
precompute_kernel(const float* __restrict__ h, const float* __restrict__ W1) {
    extern __shared__ uint32_t sm[];
    uint32_t* As = sm;               // [128][LDA] tf32 of h tile (row = node, col = k)
    uint32_t* Bs = sm + 128 * LDA;   // [128][LDA] tf32 of W1 half (row = k, col = n)

    const int tid = threadIdx.x;
    const int half = blockIdx.y;
    const long tile_base = (long)blockIdx.x * 128;

    // --- Stage A: h[tile_base + r][0:128], tf32-rounded, float4 loads ---
    for (int i = tid; i < 128 * 32; i += 256) {
        int r = i >> 5, c4 = i & 31;
        long node = tile_base + r;
        uint4 u = {0u, 0u, 0u, 0u};
        if (node < N_NODES) {
            float4 v = *reinterpret_cast<const float4*>(h + node * 128 + c4 * 4);
            u.x = cvt_rna_tf32(v.x); u.y = cvt_rna_tf32(v.y);
            u.z = cvt_rna_tf32(v.z); u.w = cvt_rna_tf32(v.w);
        }
        *reinterpret_cast<uint4*>(&As[r * LDA + c4 * 4]) = u;
    }
    // --- Stage B: W1[(half*128 + k)][n]  (row-major [256,128]) ---
    const float* W1h = W1 + (size_t)half * 128 * 128;
    for (int i = tid; i < 128 * 32; i += 256) {
        int k = i >> 5, c4 = i & 31;
        float4 v = *reinterpret_cast<const float4*>(W1h + k * 128 + c4 * 4);
        uint4 u;
        u.x = cvt_rna_tf32(v.x); u.y = cvt_rna_tf32(v.y);
        u.z = cvt_rna_tf32(v.z); u.w = cvt_rna_tf32(v.w);
        *reinterpret_cast<uint4*>(&Bs[k * LDA + c4 * 4]) = u;
    }
    __syncthreads();

    const int wid = tid >> 5, lane = tid & 31;
    const int g = lane >> 2, tg = lane & 3;   // groupID, threadID_in_group
    const int wm = wid & 3, wn = wid >> 2;    // 4 warps along M, 2 along N
    const int m0 = wm * 32, n0 = wn * 64;

    float acc[2][8][4];
    #pragma unroll
    for (int mt = 0; mt < 2; mt++)
        #pragma unroll
        for (int nt = 0; nt < 8; nt++)
            #pragma unroll
            for (int j = 0; j < 4; j++)
                acc[mt][nt][j] = 0.0f;

    #pragma unroll 4
    for (int ks = 0; ks < 16; ks++) {
        const int k0 = ks * 8;
        uint32_t a[2][4];
        #pragma unroll
        for (int mt = 0; mt < 2; mt++) {
            const int row = m0 + mt * 16 + g;
            a[mt][0] = As[row * LDA + k0 + tg];
            a[mt][1] = As[(row + 8) * LDA + k0 + tg];
            a[mt][2] = As[row * LDA + k0 + tg + 4];
            a[mt][3] = As[(row + 8) * LDA + k0 + tg + 4];
        }
        uint32_t b[8][2];
        #pragma unroll
        for (int nt = 0; nt < 8; nt++) {
            const int col = n0 + nt * 8 + g;
            b[nt][0] = Bs[(k0 + tg) * LDA + col];
            b[nt][1] = Bs[(k0 + tg + 4) * LDA + col];
        }
        #pragma unroll
        for (int mt = 0; mt < 2; mt++)
            #pragma unroll
            for (int nt = 0; nt < 8; nt++)
                mma_tf32(acc[mt][nt], a[mt], b[nt]);
    }

    // --- Epilogue: D[row][col] pairs -> g_P[node*256 + half*128 + col] ---
    #pragma unroll
    for (int mt = 0; mt < 2; mt++) {
        const int row = m0 + mt * 16 + g;
        const long node0 = tile_base + row;
        const long node1 = node0 + 8;
        #pragma unroll
        for (int nt = 0; nt < 8; nt++) {
            const int col = half * 128 + n0 + nt * 8 + tg * 2;
            if (node0 < N_NODES) {
                float2 v = {acc[mt][nt][0], acc[mt][nt][1]};
                *reinterpret_cast<float2*>(g_P + node0 * 256 + col) = v;
            }
            if (node1 < N_NODES) {
                float2 v = {acc[mt][nt][2], acc[mt][nt][3]};
                *reinterpret_cast<float2*>(g_P + node1 * 256 + col) = v;
            }
        }
    }
}

// ============================================================
// Detector: are src/dst int64 (high 32-bit words all zero) or int32?
// ============================================================
__global__ void detect_kernel(const int* __restrict__ src32) {
    if (threadIdx.x == 0) {
        int any = 0;
        #pragma unroll 4
        for (int i = 0; i < 64; i++) any |= src32[2 * i + 1];
        g_idx_is64 = (any == 0) ? 1 : 0;
    }
}

// ============================================================
// Kernel B: warp per edge.
// score[e] = b2 + sum_n relu(P[src][n] + P[dst][128+n] + b1[n]) * W2[n]
// ============================================================
__global__ void __launch_bounds__(256)
edge_kernel(const void* __restrict__ src, const void* __restrict__ dst,
            const float* __restrict__ b1, const float* __restrict__ W2,
            const float* __restrict__ b2, float* __restrict__ out, int E) {
    const int lid = threadIdx.x & 31;
    const int gw = (blockIdx.x * blockDim.x + threadIdx.x) >> 5;
    const int nw = (gridDim.x * blockDim.x) >> 5;

    const float4 b1v = reinterpret_cast<const float4*>(b1)[lid];
    const float4 w2v = reinterpret_cast<const float4*>(W2)[lid];
    const float b2v = b2[0];
    const int is64 = g_idx_is64;

    for (int e = gw; e < E; e += nw) {
        long s, d;
        if (is64) {
            s = (long)reinterpret_cast<const long long*>(src)[e];
            d = (long)reinterpret_cast<const long long*>(dst)[e];
        } else {
            s = reinterpret_cast<const int*>(src)[e];
            d = reinterpret_cast<const int*>(dst)[e];
        }
        const float4 a = reinterpret_cast<const float4*>(g_P + (size_t)s * 256)[lid];
        const float4 b = reinterpret_cast<const float4*>(g_P + (size_t)d * 256 + 128)[lid];

        float x0 = fmaxf(a.x + b.x + b1v.x, 0.0f);
        float x1 = fmaxf(a.y + b.y + b1v.y, 0.0f);
        float x2 = fmaxf(a.z + b.z + b1v.z, 0.0f);
        float x3 = fmaxf(a.w + b.w + b1v.w, 0.0f);

        float acc = x0 * w2v.x + x1 * w2v.y + x2 * w2v.z + x3 * w2v.w;
        #pragma unroll
        for (int m = 16; m > 0; m >>= 1)
            acc += __shfl_xor_sync(0xFFFFFFFFu, acc, m);
        if (lid == 0) out[e] = acc + b2v;
    }
}

// ============================================================
// Launch
// ============================================================
extern "C" void kernel_launch(void* const* d_in, const int* in_sizes, int n_in,
                              void* d_out, int out_size) {
    const float* h   = (const float*)d_in[0];
    const void*  src = d_in[1];
    const void*  dst = d_in[2];
    const float* W1  = (const float*)d_in[3];
    const float* b1  = (const float*)d_in[4];
    const float* W2  = (const float*)d_in[5];
    const float* b2  = (const float*)d_in[6];
    float* out = (float*)d_out;
    const int E = out_size;  // one score per edge
    (void)in_sizes; (void)n_in;

    const int smem_bytes = 2 * 128 * LDA * 4;  // 135168
    cudaFuncSetAttribute(precompute_kernel,
                         cudaFuncAttributeMaxDynamicSharedMemorySize, smem_bytes);

    dim3 grid((N_NODES + 127) / 128, 2);  // 782 x 2 halves
    precompute_kernel<<<grid, 256, smem_bytes>>>(h, W1);
    detect_kernel<<<1, 32>>>((const int*)src);
    edge_kernel<<<1184, 256>>>(src, dst, b1, W2, b2, out, E);
}

// round 8
// speedup vs baseline: 1.3713x; 1.3713x over previous
#include <cuda_runtime.h>
#include <cuda_fp16.h>
#include <cstdint>

// ============================================================
// Problem constants
// ============================================================
#define N_NODES 100000
#define H_FEATS 128

// P[node][0:128] = h[node] @ W1[0:128,:]   (src half)
// P[node][128:256] = h[node] @ W1[128:256,:] (dst half)
// Stored fp16: 51.2 MB -> L2-resident, halves edge-gather traffic.
__device__ __align__(16) __half g_Ph[(size_t)N_NODES * 256];
__device__ int g_idx_is64;

// ============================================================
// Helpers
// ============================================================
__device__ __forceinline__ uint32_t smem_u32(const void* p) {
    uint32_t a;
    asm("{ .reg .u64 t; cvta.to.shared.u64 t, %1; cvt.u32.u64 %0, t; }"
        : "=r"(a) : "l"(p));
    return a;
}

__device__ __forceinline__ uint32_t cvt_rna_tf32(float x) {
    uint32_t r;
    asm("cvt.rna.tf32.f32 %0, %1;" : "=r"(r) : "f"(x));
    return r;
}

// 16B async copy, with src-size (0 => zero-fill) for OOB rows
__device__ __forceinline__ void cp_async16(uint32_t dst_smem, const void* src, int src_bytes) {
    asm volatile("cp.async.cg.shared.global [%0], [%1], 16, %2;"
                 :: "r"(dst_smem), "l"(src), "r"(src_bytes) : "memory");
}
__device__ __forceinline__ void cp_async_commit_wait0() {
    asm volatile("cp.async.commit_group;" ::: "memory");
    asm volatile("cp.async.wait_group 0;" ::: "memory");
}

// mma.sync m16n8k8 tf32, f32 accumulate (sm_80 baseline PTX; legal on compute_103)
__device__ __forceinline__ void mma_tf32(float* c, const uint32_t* a, const uint32_t* b) {
    asm volatile(
        "mma.sync.aligned.m16n8k8.row.col.f32.tf32.tf32.f32 "
        "{%0,%1,%2,%3}, {%4,%5,%6,%7}, {%8,%9}, {%0,%1,%2,%3};"
        : "+f"(c[0]), "+f"(c[1]), "+f"(c[2]), "+f"(c[3])
        : "r"(a[0]), "r"(a[1]), "r"(a[2]), "r"(a[3]),
          "r"(b[0]), "r"(b[1]));
}

// ============================================================
// Kernel A: P[node][0:256] = h[node] @ [W1a | W1b]  in one pass.
// CTA tile: M=128 nodes, N=256 outs, K=128. 512 threads, 16 warps (4x4),
// warp tile 32x64. A/B staged raw fp32 via cp.async; tf32 cvt in registers.
// Epilogue staged through smem (reusing A buffer) as fp16, coalesced out.
// ============================================================
#define LDA 132   // floats per A row (128 + 4 pad)
#define LDB 264   // floats per B row (256 + 8 pad)
#define LDO 264   // halves per out-stage row (256 + 8 pad)
#define SMEM_BYTES ((128 * LDA + 128 * LDB) * 4)   // 202752

__global__ void __launch_bounds__(512, 1)
precompute_kernel(const float* __restrict__ h, const float* __restrict__ W1) {
    extern __shared__ float smf[];
    float* As = smf;                    // [128][LDA]
    float* Bs = smf + 128 * LDA;        // [128][LDB]  Bs[k][n], n in 0..255
    __half* Po = reinterpret_cast<__half*>(smf);  // reuse A region: [128][LDO]

    const int tid = threadIdx.x;
    const long tile_base = (long)blockIdx.x * 128;
    const uint32_t As_u = smem_u32(As);
    const uint32_t Bs_u = smem_u32(Bs);

    // --- Stage A: h rows (raw fp32), zero-fill OOB rows ---
    #pragma unroll
    for (int i = tid; i < 128 * 32; i += 512) {
        int r = i >> 5, c4 = i & 31;
        long node = tile_base + r;
        const float* src = h + node * 128 + c4 * 4;
        int sz = (node < N_NODES) ? 16 : 0;
        cp_async16(As_u + (uint32_t)(r * LDA + c4 * 4) * 4, src, sz);
    }
    // --- Stage B: W1[256][128] row-major; rows<128 -> src half (n=c),
    //     rows>=128 -> dst half (n=128+c). Bs[k][n] = W1[half*128+k][n'] ---
    #pragma unroll
    for (int i = tid; i < 256 * 32; i += 512) {
        int r = i >> 5, c4 = i & 31;
        const float* src = W1 + r * 128 + c4 * 4;
        int krow = r & 127;
        int nbase = (r >> 7) * 128;
        cp_async16(Bs_u + (uint32_t)(krow * LDB + nbase + c4 * 4) * 4, src, 16);
    }
    cp_async_commit_wait0();
    __syncthreads();

    // --- Compute: 16 warps, 4 along M x 4 along N, warp tile 32x64 ---
    const int wid = tid >> 5, lane = tid & 31;
    const int g = lane >> 2, tg = lane & 3;
    const int wm = wid & 3, wn = wid >> 2;
    const int m0 = wm * 32, n0 = wn * 64;

    float acc[2][8][4];
    #pragma unroll
    for (int mt = 0; mt < 2; mt++)
        #pragma unroll
        for (int nt = 0; nt < 8; nt++)
            #pragma unroll
            for (int j = 0; j < 4; j++)
                acc[mt][nt][j] = 0.0f;

    #pragma unroll 4
    for (int ks = 0; ks < 16; ks++) {
        const int k0 = ks * 8;
        uint32_t a[2][4];
        #pragma unroll
        for (int mt = 0; mt < 2; mt++) {
            const int row = m0 + mt * 16 + g;
            a[mt][0] = cvt_rna_tf32(As[row * LDA + k0 + tg]);
            a[mt][1] = cvt_rna_tf32(As[(row + 8) * LDA + k0 + tg]);
            a[mt][2] = cvt_rna_tf32(As[row * LDA + k0 + tg + 4]);
            a[mt][3] = cvt_rna_tf32(As[(row + 8) * LDA + k0 + tg + 4]);
        }
        uint32_t b[8][2];
        #pragma unroll
        for (int nt = 0; nt < 8; nt++) {
            const int col = n0 + nt * 8 + g;
            b[nt][0] = cvt_rna_tf32(Bs[(k0 + tg) * LDB + col]);
            b[nt][1] = cvt_rna_tf32(Bs[(k0 + tg + 4) * LDB + col]);
        }
        #pragma unroll
        for (int mt = 0; mt < 2; mt++)
            #pragma unroll
            for (int nt = 0; nt < 8; nt++)
                mma_tf32(acc[mt][nt], a[mt], b[nt]);
    }

    __syncthreads();  // all warps done reading As before we overwrite it as Po

    // --- Stage acc -> Po (fp16) in smem, conflict-free half2 stores ---
    #pragma unroll
    for (int mt = 0; mt < 2; mt++) {
        const int row0 = m0 + mt * 16 + g;
        #pragma unroll
        for (int nt = 0; nt < 8; nt++) {
            const int col = n0 + nt * 8 + tg * 2;
            *reinterpret_cast<__half2*>(Po + row0 * LDO + col) =
                __floats2half2_rn(acc[mt][nt][0], acc[mt][nt][1]);
            *reinterpret_cast<__half2*>(Po + (row0 + 8) * LDO + col) =
                __floats2half2_rn(acc[mt][nt][2], acc[mt][nt][3]);
        }
    }
    __syncthreads();

    // --- Coalesced copy-out: 512B per node row ---
    #pragma unroll
    for (int i = tid; i < 128 * 32; i += 512) {
        int r = i >> 5, c = i & 31;
        long node = tile_base + r;
        if (node < N_NODES) {
            uint4 v = *reinterpret_cast<const uint4*>(Po + r * LDO + c * 8);
            *reinterpret_cast<uint4*>(g_Ph + node * 256 + c * 8) = v;
        }
    }
}

// ============================================================
// Detector: are src/dst int64 (high 32-bit words all zero) or int32?
// ============================================================
__global__ void detect_kernel(const int* __restrict__ src32) {
    if (threadIdx.x == 0) {
        int any = 0;
        #pragma unroll 4
        for (int i = 0; i < 64; i++) any |= src32[2 * i + 1];
        g_idx_is64 = (any == 0) ? 1 : 0;
    }
}

// ============================================================
// Kernel B: 16 lanes per edge, 2 edges per warp.
// score[e] = b2 + sum_n relu(P[src][n] + P[dst][128+n] + b1[n]) * W2[n]
// ============================================================
__global__ void __launch_bounds__(256)
edge_kernel(const void* __restrict__ src, const void* __restrict__ dst,
            const float* __restrict__ b1, const float* __restrict__ W2,
            const float* __restrict__ b2, float* __restrict__ out, int E) {
    const int lane = threadIdx.x & 31;
    const int sub = lane >> 4;      // which edge within the warp
    const int l16 = lane & 15;
    const int gw = (blockIdx.x * blockDim.x + threadIdx.x) >> 5;
    const int nw = (gridDim.x * blockDim.x) >> 5;
    const int npairs = (E + 1) >> 1;

    // 8 features per lane
    const float4 b1lo = reinterpret_cast<const float4*>(b1)[l16 * 2];
    const float4 b1hi = reinterpret_cast<const float4*>(b1)[l16 * 2 + 1];
    const float4 w2lo = reinterpret_cast<const float4*>(W2)[l16 * 2];
    const float4 w2hi = reinterpret_cast<const float4*>(W2)[l16 * 2 + 1];
    const float b2v = b2[0];
    const int is64 = g_idx_is64;

    for (int p = gw; p < npairs; p += nw) {
        const int e = p * 2 + sub;
        long s, d;
        if (e < E) {
            if (is64) {
                s = (long)reinterpret_cast<const long long*>(src)[e];
                d = (long)reinterpret_cast<const long long*>(dst)[e];
            } else {
                s = reinterpret_cast<const int*>(src)[e];
                d = reinterpret_cast<const int*>(dst)[e];
            }
        } else {
            s = 0; d = 0;
        }

        const uint4 av = reinterpret_cast<const uint4*>(g_Ph + (size_t)s * 256)[l16];
        const uint4 bv = reinterpret_cast<const uint4*>(g_Ph + (size_t)d * 256 + 128)[l16];
        const __half2* ah = reinterpret_cast<const __half2*>(&av);
        const __half2* bh = reinterpret_cast<const __half2*>(&bv);

        float2 fa0 = __half22float2(ah[0]), fb0 = __half22float2(bh[0]);
        float2 fa1 = __half22float2(ah[1]), fb1 = __half22float2(bh[1]);
        float2 fa2 = __half22float2(ah[2]), fb2 = __half22float2(bh[2]);
        float2 fa3 = __half22float2(ah[3]), fb3 = __half22float2(bh[3]);

        float x0 = fmaxf(fa0.x + fb0.x + b1lo.x, 0.0f);
        float x1 = fmaxf(fa0.y + fb0.y + b1lo.y, 0.0f);
        float x2 = fmaxf(fa1.x + fb1.x + b1lo.z, 0.0f);
        float x3 = fmaxf(fa1.y + fb1.y + b1lo.w, 0.0f);
        float x4 = fmaxf(fa2.x + fb2.x + b1hi.x, 0.0f);
        float x5 = fmaxf(fa2.y + fb2.y + b1hi.y, 0.0f);
        float x6 = fmaxf(fa3.x + fb3.x + b1hi.z, 0.0f);
        float x7 = fmaxf(fa3.y + fb3.y + b1hi.w, 0.0f);

        float acc = x0 * w2lo.x + x1 * w2lo.y + x2 * w2lo.z + x3 * w2lo.w
                  + x4 * w2hi.x + x5 * w2hi.y + x6 * w2hi.z + x7 * w2hi.w;

        #pragma unroll
        for (int m = 8; m > 0; m >>= 1)
            acc += __shfl_xor_sync(0xFFFFFFFFu, acc, m);

        if (l16 == 0 && e < E) out[e] = acc + b2v;
    }
}

// ============================================================
// Launch
// ============================================================
extern "C" void kernel_launch(void* const* d_in, const int* in_sizes, int n_in,
                              void* d_out, int out_size) {
    const float* h   = (const float*)d_in[0];
    const void*  src = d_in[1];
    const void*  dst = d_in[2];
    const float* W1  = (const float*)d_in[3];
    const float* b1  = (const float*)d_in[4];
    const float* W2  = (const float*)d_in[5];
    const float* b2  = (const float*)d_in[6];
    float* out = (float*)d_out;
    const int E = out_size;  // one score per edge
    (void)in_sizes; (void)n_in;

    cudaFuncSetAttribute(precompute_kernel,
                         cudaFuncAttributeMaxDynamicSharedMemorySize, SMEM_BYTES);

    const int tiles = (N_NODES + 127) / 128;  // 782
    precompute_kernel<<<tiles, 512, SMEM_BYTES>>>(h, W1);
    detect_kernel<<<1, 32>>>((const int*)src);
    edge_kernel<<<1184, 256>>>(src, dst, b1, W2, b2, out, E);
}

// round 9
// speedup vs baseline: 2.1472x; 1.5658x over previous
#include <cuda_runtime.h>
#include <cuda_fp16.h>
#include <cstdint>

// ============================================================
// Problem constants
// ============================================================
#define N_NODES 100000
#define H_FEATS 128

// P[node][0:128] = h[node] @ W1[0:128,:]   (src half)
// P[node][128:256] = h[node] @ W1[128:256,:] (dst half)
// Stored fp16: 51.2 MB -> L2-resident, halves edge-gather traffic.
__device__ __align__(16) __half g_Ph[(size_t)N_NODES * 256];
__device__ int g_idx_is64;

// ============================================================
// Helpers
// ============================================================
__device__ __forceinline__ uint32_t smem_u32(const void* p) {
    uint32_t a;
    asm("{ .reg .u64 t; cvta.to.shared.u64 t, %1; cvt.u32.u64 %0, t; }"
        : "=r"(a) : "l"(p));
    return a;
}

__device__ __forceinline__ uint32_t cvt_rna_tf32(float x) {
    uint32_t r;
    asm("cvt.rna.tf32.f32 %0, %1;" : "=r"(r) : "f"(x));
    return r;
}

// 16B async copy, with src-size (0 => zero-fill) for OOB rows
__device__ __forceinline__ void cp_async16(uint32_t dst_smem, const void* src, int src_bytes) {
    asm volatile("cp.async.cg.shared.global [%0], [%1], 16, %2;"
                 :: "r"(dst_smem), "l"(src), "r"(src_bytes) : "memory");
}
__device__ __forceinline__ void cp_async_commit_wait0() {
    asm volatile("cp.async.commit_group;" ::: "memory");
    asm volatile("cp.async.wait_group 0;" ::: "memory");
}

// mma.sync m16n8k8 tf32, f32 accumulate (sm_80 baseline PTX; legal on compute_103)
__device__ __forceinline__ void mma_tf32(float* c, const uint32_t* a, const uint32_t* b) {
    asm volatile(
        "mma.sync.aligned.m16n8k8.row.col.f32.tf32.tf32.f32 "
        "{%0,%1,%2,%3}, {%4,%5,%6,%7}, {%8,%9}, {%0,%1,%2,%3};"
        : "+f"(c[0]), "+f"(c[1]), "+f"(c[2]), "+f"(c[3])
        : "r"(a[0]), "r"(a[1]), "r"(a[2]), "r"(a[3]),
          "r"(b[0]), "r"(b[1]));
}

// ============================================================
// Kernel A: P[node][0:256] = h[node] @ [W1a | W1b]  in one pass.
// CTA tile: M=128 nodes, N=256 outs, K=128. 512 threads, 16 warps (4x4),
// warp tile 32x64. Stage raw fp32 via cp.async, then ONE in-place
// tf32-convert pass over smem -> mainloop is pure LDS+MMA.
// Epilogue staged through smem (reusing A buffer) as fp16, coalesced out.
// ============================================================
#define LDA 132   // floats per A row (128 + 4 pad)
#define LDB 264   // floats per B row (256 + 8 pad)
#define LDO 264   // halves per out-stage row (256 + 8 pad)
#define SMEM_BYTES ((128 * LDA + 128 * LDB) * 4)   // 202752

__global__ void __launch_bounds__(512, 1)
precompute_kernel(const float* __restrict__ h, const float* __restrict__ W1) {
    extern __shared__ float smf[];
    float* As = smf;                    // [128][LDA]
    float* Bs = smf + 128 * LDA;        // [128][LDB]  Bs[k][n], n in 0..255
    uint32_t* As32 = reinterpret_cast<uint32_t*>(As);
    uint32_t* Bs32 = reinterpret_cast<uint32_t*>(Bs);
    __half* Po = reinterpret_cast<__half*>(smf);  // reuse A region: [128][LDO]

    const int tid = threadIdx.x;
    const long tile_base = (long)blockIdx.x * 128;
    const uint32_t As_u = smem_u32(As);
    const uint32_t Bs_u = smem_u32(Bs);

    // --- Stage A: h rows (raw fp32), zero-fill OOB rows ---
    #pragma unroll
    for (int i = tid; i < 128 * 32; i += 512) {
        int r = i >> 5, c4 = i & 31;
        long node = tile_base + r;
        const float* src = h + node * 128 + c4 * 4;
        int sz = (node < N_NODES) ? 16 : 0;
        cp_async16(As_u + (uint32_t)(r * LDA + c4 * 4) * 4, src, sz);
    }
    // --- Stage B: W1[256][128] row-major; rows<128 -> src half (n=c),
    //     rows>=128 -> dst half (n=128+c). Bs[k][n] = W1[half*128+k][n'] ---
    #pragma unroll
    for (int i = tid; i < 256 * 32; i += 512) {
        int r = i >> 5, c4 = i & 31;
        const float* src = W1 + r * 128 + c4 * 4;
        int krow = r & 127;
        int nbase = (r >> 7) * 128;
        cp_async16(Bs_u + (uint32_t)(krow * LDB + nbase + c4 * 4) * 4, src, 16);
    }
    cp_async_commit_wait0();
    __syncthreads();

    // --- In-place fp32 -> tf32 convert (each thread owns its uint4s) ---
    #pragma unroll
    for (int i = tid; i < 128 * 32; i += 512) {
        int r = i >> 5, c4 = i & 31;
        float4 v = *reinterpret_cast<const float4*>(&As[r * LDA + c4 * 4]);
        uint4 u;
        u.x = cvt_rna_tf32(v.x); u.y = cvt_rna_tf32(v.y);
        u.z = cvt_rna_tf32(v.z); u.w = cvt_rna_tf32(v.w);
        *reinterpret_cast<uint4*>(&As32[r * LDA + c4 * 4]) = u;
    }
    #pragma unroll
    for (int i = tid; i < 128 * 64; i += 512) {
        int r = i >> 6, c4 = i & 63;
        float4 v = *reinterpret_cast<const float4*>(&Bs[r * LDB + c4 * 4]);
        uint4 u;
        u.x = cvt_rna_tf32(v.x); u.y = cvt_rna_tf32(v.y);
        u.z = cvt_rna_tf32(v.z); u.w = cvt_rna_tf32(v.w);
        *reinterpret_cast<uint4*>(&Bs32[r * LDB + c4 * 4]) = u;
    }
    __syncthreads();

    // --- Compute: 16 warps, 4 along M x 4 along N, warp tile 32x64 ---
    const int wid = tid >> 5, lane = tid & 31;
    const int g = lane >> 2, tg = lane & 3;
    const int wm = wid & 3, wn = wid >> 2;
    const int m0 = wm * 32, n0 = wn * 64;

    float acc[2][8][4];
    #pragma unroll
    for (int mt = 0; mt < 2; mt++)
        #pragma unroll
        for (int nt = 0; nt < 8; nt++)
            #pragma unroll
            for (int j = 0; j < 4; j++)
                acc[mt][nt][j] = 0.0f;

    #pragma unroll 4
    for (int ks = 0; ks < 16; ks++) {
        const int k0 = ks * 8;
        uint32_t a[2][4];
        #pragma unroll
        for (int mt = 0; mt < 2; mt++) {
            const int row = m0 + mt * 16 + g;
            a[mt][0] = As32[row * LDA + k0 + tg];
            a[mt][1] = As32[(row + 8) * LDA + k0 + tg];
            a[mt][2] = As32[row * LDA + k0 + tg + 4];
            a[mt][3] = As32[(row + 8) * LDA + k0 + tg + 4];
        }
        uint32_t b[8][2];
        #pragma unroll
        for (int nt = 0; nt < 8; nt++) {
            const int col = n0 + nt * 8 + g;
            b[nt][0] = Bs32[(k0 + tg) * LDB + col];
            b[nt][1] = Bs32[(k0 + tg + 4) * LDB + col];
        }
        #pragma unroll
        for (int mt = 0; mt < 2; mt++)
            #pragma unroll
            for (int nt = 0; nt < 8; nt++)
                mma_tf32(acc[mt][nt], a[mt], b[nt]);
    }

    __syncthreads();  // all warps done reading As before we overwrite it as Po

    // --- Stage acc -> Po (fp16) in smem, conflict-free half2 stores ---
    #pragma unroll
    for (int mt = 0; mt < 2; mt++) {
        const int row0 = m0 + mt * 16 + g;
        #pragma unroll
        for (int nt = 0; nt < 8; nt++) {
            const int col = n0 + nt * 8 + tg * 2;
            *reinterpret_cast<__half2*>(Po + row0 * LDO + col) =
                __floats2half2_rn(acc[mt][nt][0], acc[mt][nt][1]);
            *reinterpret_cast<__half2*>(Po + (row0 + 8) * LDO + col) =
                __floats2half2_rn(acc[mt][nt][2], acc[mt][nt][3]);
        }
    }
    __syncthreads();

    // --- Coalesced copy-out: 512B per node row ---
    #pragma unroll
    for (int i = tid; i < 128 * 32; i += 512) {
        int r = i >> 5, c = i & 31;
        long node = tile_base + r;
        if (node < N_NODES) {
            uint4 v = *reinterpret_cast<const uint4*>(Po + r * LDO + c * 8);
            *reinterpret_cast<uint4*>(g_Ph + node * 256 + c * 8) = v;
        }
    }
}

// ============================================================
// Detector: are src/dst int64 (high 32-bit words all zero) or int32?
// ============================================================
__global__ void detect_kernel(const int* __restrict__ src32) {
    if (threadIdx.x == 0) {
        int any = 0;
        #pragma unroll 4
        for (int i = 0; i < 64; i++) any |= src32[2 * i + 1];
        g_idx_is64 = (any == 0) ? 1 : 0;
    }
}

// ============================================================
// Kernel B: 16 lanes per edge, 2 edges per 16-lane group per iter
// (4 edges in flight per warp). All gathers issued before compute.
// score[e] = b2 + sum_n relu(P[src][n] + P[dst][128+n] + b1[n]) * W2[n]
// ============================================================
__global__ void __launch_bounds__(256)
edge_kernel(const void* __restrict__ src, const void* __restrict__ dst,
            const float* __restrict__ b1, const float* __restrict__ W2,
            const float* __restrict__ b2, float* __restrict__ out, int E) {
    const int lane = threadIdx.x & 31;
    const int sub = lane >> 4;      // which edge-pair slot within the warp
    const int l16 = lane & 15;
    const int gw = (blockIdx.x * blockDim.x + threadIdx.x) >> 5;
    const int nw = (gridDim.x * blockDim.x) >> 5;
    const int nquads = (E + 3) >> 2;

    // 8 features per lane
    const float4 b1lo = reinterpret_cast<const float4*>(b1)[l16 * 2];
    const float4 b1hi = reinterpret_cast<const float4*>(b1)[l16 * 2 + 1];
    const float4 w2lo = reinterpret_cast<const float4*>(W2)[l16 * 2];
    const float4 w2hi = reinterpret_cast<const float4*>(W2)[l16 * 2 + 1];
    const float b2v = b2[0];
    const int is64 = g_idx_is64;
    const long long* src64 = reinterpret_cast<const long long*>(src);
    const long long* dst64 = reinterpret_cast<const long long*>(dst);
    const int* src32 = reinterpret_cast<const int*>(src);
    const int* dst32 = reinterpret_cast<const int*>(dst);

    for (int q = gw; q < nquads; q += nw) {
        const int e0 = q * 4 + sub * 2;
        const int e1 = e0 + 1;

        // --- All index loads first ---
        long s0 = 0, d0 = 0, s1 = 0, d1 = 0;
        if (is64) {
            if (e0 < E) { s0 = (long)src64[e0]; d0 = (long)dst64[e0]; }
            if (e1 < E) { s1 = (long)src64[e1]; d1 = (long)dst64[e1]; }
        } else {
            if (e0 < E) { s0 = src32[e0]; d0 = dst32[e0]; }
            if (e1 < E) { s1 = src32[e1]; d1 = dst32[e1]; }
        }

        // --- All gathers issued back-to-back (4 independent LDG.128) ---
        const uint4 av0 = reinterpret_cast<const uint4*>(g_Ph + (size_t)s0 * 256)[l16];
        const uint4 bv0 = reinterpret_cast<const uint4*>(g_Ph + (size_t)d0 * 256 + 128)[l16];
        const uint4 av1 = reinterpret_cast<const uint4*>(g_Ph + (size_t)s1 * 256)[l16];
        const uint4 bv1 = reinterpret_cast<const uint4*>(g_Ph + (size_t)d1 * 256 + 128)[l16];

        // --- Compute both edges ---
        float acc0, acc1;
        {
            const __half2* ah = reinterpret_cast<const __half2*>(&av0);
            const __half2* bh = reinterpret_cast<const __half2*>(&bv0);
            float2 fa0 = __half22float2(ah[0]), fb0 = __half22float2(bh[0]);
            float2 fa1 = __half22float2(ah[1]), fb1 = __half22float2(bh[1]);
            float2 fa2 = __half22float2(ah[2]), fb2 = __half22float2(bh[2]);
            float2 fa3 = __half22float2(ah[3]), fb3 = __half22float2(bh[3]);
            float x0 = fmaxf(fa0.x + fb0.x + b1lo.x, 0.0f);
            float x1 = fmaxf(fa0.y + fb0.y + b1lo.y, 0.0f);
            float x2 = fmaxf(fa1.x + fb1.x + b1lo.z, 0.0f);
            float x3 = fmaxf(fa1.y + fb1.y + b1lo.w, 0.0f);
            float x4 = fmaxf(fa2.x + fb2.x + b1hi.x, 0.0f);
            float x5 = fmaxf(fa2.y + fb2.y + b1hi.y, 0.0f);
            float x6 = fmaxf(fa3.x + fb3.x + b1hi.z, 0.0f);
            float x7 = fmaxf(fa3.y + fb3.y + b1hi.w, 0.0f);
            acc0 = x0 * w2lo.x + x1 * w2lo.y + x2 * w2lo.z + x3 * w2lo.w
                 + x4 * w2hi.x + x5 * w2hi.y + x6 * w2hi.z + x7 * w2hi.w;
        }
        {
            const __half2* ah = reinterpret_cast<const __half2*>(&av1);
            const __half2* bh = reinterpret_cast<const __half2*>(&bv1);
            float2 fa0 = __half22float2(ah[0]), fb0 = __half22float2(bh[0]);
            float2 fa1 = __half22float2(ah[1]), fb1 = __half22float2(bh[1]);
            float2 fa2 = __half22float2(ah[2]), fb2 = __half22float2(bh[2]);
            float2 fa3 = __half22float2(ah[3]), fb3 = __half22float2(bh[3]);
            float x0 = fmaxf(fa0.x + fb0.x + b1lo.x, 0.0f);
            float x1 = fmaxf(fa0.y + fb0.y + b1lo.y, 0.0f);
            float x2 = fmaxf(fa1.x + fb1.x + b1lo.z, 0.0f);
            float x3 = fmaxf(fa1.y + fb1.y + b1lo.w, 0.0f);
            float x4 = fmaxf(fa2.x + fb2.x + b1hi.x, 0.0f);
            float x5 = fmaxf(fa2.y + fb2.y + b1hi.y, 0.0f);
            float x6 = fmaxf(fa3.x + fb3.x + b1hi.z, 0.0f);
            float x7 = fmaxf(fa3.y + fb3.y + b1hi.w, 0.0f);
            acc1 = x0 * w2lo.x + x1 * w2lo.y + x2 * w2lo.z + x3 * w2lo.w
                 + x4 * w2hi.x + x5 * w2hi.y + x6 * w2hi.z + x7 * w2hi.w;
        }

        // --- Shared reduction tree over 16 lanes for both edges ---
        #pragma unroll
        for (int m = 8; m > 0; m >>= 1) {
            acc0 += __shfl_xor_sync(0xFFFFFFFFu, acc0, m);
            acc1 += __shfl_xor_sync(0xFFFFFFFFu, acc1, m);
        }

        if (l16 == 0) {
            if (e0 < E) out[e0] = acc0 + b2v;
            if (e1 < E) out[e1] = acc1 + b2v;
        }
    }
}

// ============================================================
// Launch
// ============================================================
extern "C" void kernel_launch(void* const* d_in, const int* in_sizes, int n_in,
                              void* d_out, int out_size) {
    const float* h   = (const float*)d_in[0];
    const void*  src = d_in[1];
    const void*  dst = d_in[2];
    const float* W1  = (const float*)d_in[3];
    const float* b1  = (const float*)d_in[4];
    const float* W2  = (const float*)d_in[5];
    const float* b2  = (const float*)d_in[6];
    float* out = (float*)d_out;
    const int E = out_size;  // one score per edge
    (void)in_sizes; (void)n_in;

    cudaFuncSetAttribute(precompute_kernel,
                         cudaFuncAttributeMaxDynamicSharedMemorySize, SMEM_BYTES);

    const int tiles = (N_NODES + 127) / 128;  // 782
    precompute_kernel<<<tiles, 512, SMEM_BYTES>>>(h, W1);
    detect_kernel<<<1, 32>>>((const int*)src);
    edge_kernel<<<1184, 256>>>(src, dst, b1, W2, b2, out, E);
}

// round 10
// speedup vs baseline: 3.0230x; 1.4079x over previous
#include <cuda_runtime.h>
#include <cuda_fp16.h>
#include <cstdint>

// ============================================================
// Problem constants
// ============================================================
#define N_NODES 100000
#define H_FEATS 128

// P[node][0:128] = h[node] @ W1[0:128,:]   (src half)
// P[node][128:256] = h[node] @ W1[128:256,:] (dst half)
// Stored fp16: 51.2 MB -> L2-resident, halves edge-gather traffic.
__device__ __align__(16) __half g_Ph[(size_t)N_NODES * 256];
__device__ int g_idx_is64;

// ============================================================
// Helpers
// ============================================================
// mma.sync m16n8k16 fp16 in, fp32 accum (sm_80 baseline PTX; legal on compute_103)
__device__ __forceinline__ void mma_f16(float* c, const uint32_t* a, const uint32_t* b) {
    asm volatile(
        "mma.sync.aligned.m16n8k16.row.col.f32.f16.f16.f32 "
        "{%0,%1,%2,%3}, {%4,%5,%6,%7}, {%8,%9}, {%0,%1,%2,%3};"
        : "+f"(c[0]), "+f"(c[1]), "+f"(c[2]), "+f"(c[3])
        : "r"(a[0]), "r"(a[1]), "r"(a[2]), "r"(a[3]),
          "r"(b[0]), "r"(b[1]));
}

__device__ __forceinline__ uint32_t pack_h2(float x, float y) {
    __half2 h = __floats2half2_rn(x, y);
    return *reinterpret_cast<uint32_t*>(&h);
}

// ============================================================
// Kernel A: P[node][half*128:+128] = h[node] @ W1[half*128:+128, :]
// CTA: M=128 nodes, N=128, K=128. 256 threads, 8 warps (4M x 2N),
// warp tile 32x64, fp16 m16n8k16. 2 CTAs/SM (68.6KB smem, <=128 regs).
// A packed: Ap[row][kh] = half2(A[row][2kh], A[row][2kh+1])
// B packed: Bp[kh][n]  = half2(W[2kh][n],  W[2kh+1][n])
// ============================================================
#define LDAP 68    // half2 per A row (64 + 4 pad)   -> bank 4g+tg, bijective
#define LDBP 136   // half2 per B row (128 + 8 pad)  -> bank 8tg+g, bijective
#define LDOW 68    // words per Po row (128 halves + 8 pad halves)
#define SMEM_BYTES ((128 * LDAP + 64 * LDBP) * 4)   // 34816 + 34816 = 69632

__global__ void __launch_bounds__(256, 2)
precompute_kernel(const float* __restrict__ h, const float* __restrict__ W1) {
    extern __shared__ uint32_t smw[];
    uint32_t* Ap = smw;                 // [128][LDAP] half2
    uint32_t* Bp = smw + 128 * LDAP;    // [64][LDBP]  half2
    __half* Po = reinterpret_cast<__half*>(Ap);  // reuse A region for epilogue

    const int tid = threadIdx.x;
    const int half = blockIdx.y;
    const long tile_base = (long)blockIdx.x * 128;

    // --- Stage A: h rows fp32 -> packed fp16; one warp per node row ---
    #pragma unroll
    for (int i = tid; i < 128 * 32; i += 256) {
        int r = i >> 5, c4 = i & 31;
        long node = tile_base + r;
        uint2 u = {0u, 0u};
        if (node < N_NODES) {
            float4 v = *reinterpret_cast<const float4*>(h + node * 128 + c4 * 4);
            u.x = pack_h2(v.x, v.y);
            u.y = pack_h2(v.z, v.w);
        }
        *reinterpret_cast<uint2*>(&Ap[r * LDAP + c4 * 2]) = u;
    }
    // --- Stage B: W1 row-pairs (2r2, 2r2+1) of this half -> Bp[r2][c] ---
    const float* W1h = W1 + (size_t)half * 128 * 128;
    #pragma unroll
    for (int i = tid; i < 64 * 32; i += 256) {
        int r2 = i >> 5, c4 = i & 31;
        float4 v0 = *reinterpret_cast<const float4*>(W1h + (2 * r2) * 128 + c4 * 4);
        float4 v1 = *reinterpret_cast<const float4*>(W1h + (2 * r2 + 1) * 128 + c4 * 4);
        uint4 u;
        u.x = pack_h2(v0.x, v1.x);
        u.y = pack_h2(v0.y, v1.y);
        u.z = pack_h2(v0.z, v1.z);
        u.w = pack_h2(v0.w, v1.w);
        *reinterpret_cast<uint4*>(&Bp[r2 * LDBP + c4 * 4]) = u;
    }
    __syncthreads();

    // --- Compute: 8 warps, 4 along M x 2 along N, warp tile 32x64 ---
    const int wid = tid >> 5, lane = tid & 31;
    const int g = lane >> 2, tg = lane & 3;
    const int wm = wid & 3, wn = wid >> 2;
    const int m0 = wm * 32, n0 = wn * 64;

    float acc[2][8][4];
    #pragma unroll
    for (int mt = 0; mt < 2; mt++)
        #pragma unroll
        for (int nt = 0; nt < 8; nt++)
            #pragma unroll
            for (int j = 0; j < 4; j++)
                acc[mt][nt][j] = 0.0f;

    #pragma unroll
    for (int ks = 0; ks < 8; ks++) {
        const int k0h = ks * 8;   // half2 index of this k16 block
        uint32_t a[2][4];
        #pragma unroll
        for (int mt = 0; mt < 2; mt++) {
            const int row = m0 + mt * 16 + g;
            a[mt][0] = Ap[row * LDAP + k0h + tg];
            a[mt][1] = Ap[(row + 8) * LDAP + k0h + tg];
            a[mt][2] = Ap[row * LDAP + k0h + tg + 4];
            a[mt][3] = Ap[(row + 8) * LDAP + k0h + tg + 4];
        }
        uint32_t b[8][2];
        #pragma unroll
        for (int nt = 0; nt < 8; nt++) {
            const int col = n0 + nt * 8 + g;
            b[nt][0] = Bp[(k0h + tg) * LDBP + col];
            b[nt][1] = Bp[(k0h + tg + 4) * LDBP + col];
        }
        #pragma unroll
        for (int mt = 0; mt < 2; mt++)
            #pragma unroll
            for (int nt = 0; nt < 8; nt++)
                mma_f16(acc[mt][nt], a[mt], b[nt]);
    }

    __syncthreads();  // all warps done reading Ap before overwrite as Po

    // --- Stage acc -> Po fp16 in smem (conflict-free half2 stores) ---
    #pragma unroll
    for (int mt = 0; mt < 2; mt++) {
        const int row0 = m0 + mt * 16 + g;
        #pragma unroll
        for (int nt = 0; nt < 8; nt++) {
            const int colw = (n0 + nt * 8 + tg * 2) >> 1;  // half2 index in row
            reinterpret_cast<uint32_t*>(Po)[row0 * LDOW + colw] =
                pack_h2(acc[mt][nt][0], acc[mt][nt][1]);
            reinterpret_cast<uint32_t*>(Po)[(row0 + 8) * LDOW + colw] =
                pack_h2(acc[mt][nt][2], acc[mt][nt][3]);
        }
    }
    __syncthreads();

    // --- Coalesced copy-out: 256B per node row into this half's slot ---
    #pragma unroll
    for (int i = tid; i < 128 * 16; i += 256) {
        int r = i >> 4, c = i & 15;
        long node = tile_base + r;
        if (node < N_NODES) {
            uint4 v = *reinterpret_cast<const uint4*>(
                reinterpret_cast<const uint32_t*>(Po) + r * LDOW + c * 4);
            *reinterpret_cast<uint4*>(g_Ph + node * 256 + half * 128 + c * 8) = v;
        }
    }
}

// ============================================================
// Detector: are src/dst int64 (high 32-bit words all zero) or int32?
// ============================================================
__global__ void detect_kernel(const int* __restrict__ src32) {
    if (threadIdx.x == 0) {
        int any = 0;
        #pragma unroll 4
        for (int i = 0; i < 64; i++) any |= src32[2 * i + 1];
        g_idx_is64 = (any == 0) ? 1 : 0;
    }
}

// ============================================================
// Kernel B: 16 lanes per edge, 4 edges per 16-lane group per iter
// (8 edges in flight per warp; 8 outstanding LDG.128 gathers).
// score[e] = b2 + sum_n relu(P[src][n] + P[dst][128+n] + b1[n]) * W2[n]
// ============================================================
__device__ __forceinline__ float edge_partial(
    const uint4& av, const uint4& bv,
    const float4& b1lo, const float4& b1hi,
    const float4& w2lo, const float4& w2hi) {
    const __half2* ah = reinterpret_cast<const __half2*>(&av);
    const __half2* bh = reinterpret_cast<const __half2*>(&bv);
    float2 fa0 = __half22float2(ah[0]), fb0 = __half22float2(bh[0]);
    float2 fa1 = __half22float2(ah[1]), fb1 = __half22float2(bh[1]);
    float2 fa2 = __half22float2(ah[2]), fb2 = __half22float2(bh[2]);
    float2 fa3 = __half22float2(ah[3]), fb3 = __half22float2(bh[3]);
    float x0 = fmaxf(fa0.x + fb0.x + b1lo.x, 0.0f);
    float x1 = fmaxf(fa0.y + fb0.y + b1lo.y, 0.0f);
    float x2 = fmaxf(fa1.x + fb1.x + b1lo.z, 0.0f);
    float x3 = fmaxf(fa1.y + fb1.y + b1lo.w, 0.0f);
    float x4 = fmaxf(fa2.x + fb2.x + b1hi.x, 0.0f);
    float x5 = fmaxf(fa2.y + fb2.y + b1hi.y, 0.0f);
    float x6 = fmaxf(fa3.x + fb3.x + b1hi.z, 0.0f);
    float x7 = fmaxf(fa3.y + fb3.y + b1hi.w, 0.0f);
    return x0 * w2lo.x + x1 * w2lo.y + x2 * w2lo.z + x3 * w2lo.w
         + x4 * w2hi.x + x5 * w2hi.y + x6 * w2hi.z + x7 * w2hi.w;
}

__global__ void __launch_bounds__(256)
edge_kernel(const void* __restrict__ src, const void* __restrict__ dst,
            const float* __restrict__ b1, const float* __restrict__ W2,
            const float* __restrict__ b2, float* __restrict__ out, int E) {
    const int lane = threadIdx.x & 31;
    const int sub = lane >> 4;      // group 0/1 within warp
    const int l16 = lane & 15;
    const int gw = (blockIdx.x * blockDim.x + threadIdx.x) >> 5;
    const int nw = (gridDim.x * blockDim.x) >> 5;
    const int noct = (E + 7) >> 3;  // 8 edges per warp-iter

    const float4 b1lo = reinterpret_cast<const float4*>(b1)[l16 * 2];
    const float4 b1hi = reinterpret_cast<const float4*>(b1)[l16 * 2 + 1];
    const float4 w2lo = reinterpret_cast<const float4*>(W2)[l16 * 2];
    const float4 w2hi = reinterpret_cast<const float4*>(W2)[l16 * 2 + 1];
    const float b2v = b2[0];
    const int is64 = g_idx_is64;
    const long long* src64 = reinterpret_cast<const long long*>(src);
    const long long* dst64 = reinterpret_cast<const long long*>(dst);
    const int* src32 = reinterpret_cast<const int*>(src);
    const int* dst32 = reinterpret_cast<const int*>(dst);

    for (int q = gw; q < noct; q += nw) {
        const int ebase = q * 8 + sub * 4;

        // --- All 8 index loads first ---
        long s[4], d[4];
        #pragma unroll
        for (int j = 0; j < 4; j++) {
            int e = ebase + j;
            if (e < E) {
                if (is64) { s[j] = (long)src64[e]; d[j] = (long)dst64[e]; }
                else      { s[j] = src32[e];       d[j] = dst32[e]; }
            } else { s[j] = 0; d[j] = 0; }
        }

        // --- 8 independent LDG.128 gathers, issued back-to-back ---
        uint4 av[4], bv[4];
        #pragma unroll
        for (int j = 0; j < 4; j++) {
            av[j] = reinterpret_cast<const uint4*>(g_Ph + (size_t)s[j] * 256)[l16];
            bv[j] = reinterpret_cast<const uint4*>(g_Ph + (size_t)d[j] * 256 + 128)[l16];
        }

        // --- Compute partials ---
        float acc[4];
        #pragma unroll
        for (int j = 0; j < 4; j++)
            acc[j] = edge_partial(av[j], bv[j], b1lo, b1hi, w2lo, w2hi);

        // --- Shared reduction tree over 16 lanes for all four edges ---
        #pragma unroll
        for (int m = 8; m > 0; m >>= 1) {
            #pragma unroll
            for (int j = 0; j < 4; j++)
                acc[j] += __shfl_xor_sync(0xFFFFFFFFu, acc[j], m);
        }

        if (l16 == 0) {
            #pragma unroll
            for (int j = 0; j < 4; j++) {
                int e = ebase + j;
                if (e < E) out[e] = acc[j] + b2v;
            }
        }
    }
}

// ============================================================
// Launch
// ============================================================
extern "C" void kernel_launch(void* const* d_in, const int* in_sizes, int n_in,
                              void* d_out, int out_size) {
    const float* h   = (const float*)d_in[0];
    const void*  src = d_in[1];
    const void*  dst = d_in[2];
    const float* W1  = (const float*)d_in[3];
    const float* b1  = (const float*)d_in[4];
    const float* W2  = (const float*)d_in[5];
    const float* b2  = (const float*)d_in[6];
    float* out = (float*)d_out;
    const int E = out_size;  // one score per edge
    (void)in_sizes; (void)n_in;

    cudaFuncSetAttribute(precompute_kernel,
                         cudaFuncAttributeMaxDynamicSharedMemorySize, SMEM_BYTES);

    dim3 grid((N_NODES + 127) / 128, 2);  // 782 x 2 halves
    precompute_kernel<<<grid, 256, SMEM_BYTES>>>(h, W1);
    detect_kernel<<<1, 32>>>((const int*)src);
    edge_kernel<<<1184, 256>>>(src, dst, b1, W2, b2, out, E);
}